// round 2
// baseline (speedup 1.0000x reference)
#include <cuda_runtime.h>
#include <math.h>

// Problem constants
#define BB 64
#define TT 512
#define II 128
#define HH 512
#define OO 64
#define ALPHA 0.1f

// Recurrent kernel config
#define GRID_R 128   // blocks; each owns JT=4 hidden columns
#define JT 4
#define NTH_R 512    // 16 warps; warp w owns batches 4w..4w+3

// Scratch: full hidden history [T][B][H] (64 MB)
__device__ float g_hist[(size_t)TT * BB * HH];
__device__ unsigned g_flags[GRID_R];

__global__ void reset_kernel() {
    int i = threadIdx.x;
    if (i < GRID_R) g_flags[i] = 0u;
}

__device__ __forceinline__ float4 ldcg4(const float* p) {
    return __ldcg(reinterpret_cast<const float4*>(p));
}

// ---- f32x2 packed helpers (Blackwell) ----
__device__ __forceinline__ unsigned long long pack2(float a, float b) {
    unsigned long long r;
    asm("mov.b64 %0, {%1,%2};" : "=l"(r) : "f"(a), "f"(b));
    return r;
}
__device__ __forceinline__ void fma2(unsigned long long& d,
                                     unsigned long long a,
                                     unsigned long long b) {
    asm("fma.rn.f32x2 %0, %1, %2, %3;" : "=l"(d) : "l"(a), "l"(b), "l"(d));
}
__device__ __forceinline__ float2 unpack2(unsigned long long v) {
    float2 f;
    asm("mov.b64 {%0,%1}, %2;" : "=f"(f.x), "=f"(f.y) : "l"(v));
    return f;
}

__global__ void __launch_bounds__(NTH_R, 1) rnn_recurrent(
    const float* __restrict__ x,     // [B][T][I]
    const float* __restrict__ h0,    // [B][H]
    const float* __restrict__ Win,   // [H][I]
    const float* __restrict__ Wrec,  // [H][H]
    const float* __restrict__ bias)  // [H]
{
    const int tid  = threadIdx.x;
    const int warp = tid >> 5;
    const int lane = tid & 31;
    const int j0    = blockIdx.x * JT;  // this block's hidden columns (4)
    const int bbase = warp * 4;         // this warp's batches
    const int k0 = lane * 16;           // this lane's W_rec K-chunk
    const int i0 = lane * 4;            // this lane's W_in I-chunk

    // ---- Preload weights, j-pair packed as f32x2, ONCE ----
    // wr2[p][k] = (Wrec[j0+2p][k0+k], Wrec[j0+2p+1][k0+k])
    unsigned long long wr2[2][16];
    unsigned long long wi2[2][4];
#pragma unroll
    for (int p = 0; p < 2; p++) {
        const float* r0 = Wrec + (size_t)(j0 + 2 * p) * HH + k0;
        const float* r1 = Wrec + (size_t)(j0 + 2 * p + 1) * HH + k0;
#pragma unroll
        for (int k = 0; k < 16; k++)
            wr2[p][k] = pack2(__ldg(r0 + k), __ldg(r1 + k));
        const float* q0 = Win + (size_t)(j0 + 2 * p) * II + i0;
        const float* q1 = Win + (size_t)(j0 + 2 * p + 1) * II + i0;
#pragma unroll
        for (int i = 0; i < 4; i++)
            wi2[p][i] = pack2(__ldg(q0 + i), __ldg(q1 + i));
    }

    // Epilogue ownership for lanes 0..15: idx = 8*b0+4*b1+2*b2+b3
    const int b0 = lane & 1, b1 = (lane >> 1) & 1, b2 = (lane >> 2) & 1, b3 = (lane >> 3) & 1;
    const int bb_e = 2 * b0 + b1;          // batch slot within warp
    const int jj_e = 2 * b2 + b3;          // j slot within block
    float bj = 0.0f;
    if (lane < 16) bj = bias[j0 + jj_e];

    // acc2[bb][p]: f32x2 accumulator over (jj=2p, jj=2p+1)
    unsigned long long acc2[4][2];

    // ---- Prologue: x-projection for t=0 ----
#pragma unroll
    for (int bb = 0; bb < 4; bb++) {
        acc2[bb][0] = 0ULL; acc2[bb][1] = 0ULL;
        float4 xv = __ldg(reinterpret_cast<const float4*>(
            x + ((size_t)(bbase + bb) * TT + 0) * II + i0));
        float xs[4] = {xv.x, xv.y, xv.z, xv.w};
#pragma unroll
        for (int i = 0; i < 4; i++) {
            unsigned long long xx = pack2(xs[i], xs[i]);
            fma2(acc2[bb][0], xx, wi2[0][i]);
            fma2(acc2[bb][1], xx, wi2[1][i]);
        }
    }

    for (int t = 0; t < TT; ++t) {
        const float* hprev = (t == 0) ? h0 : (g_hist + (size_t)(t - 1) * BB * HH);

        // issue h_old load early (hidden under dot-product)
        float hold = 0.0f;
        if (lane < 16)
            hold = __ldcg(hprev + (size_t)(bbase + bb_e) * HH + j0 + jj_e);

        // ---- recurrent dot: h · W_rec^T (j-pair packed) ----
#pragma unroll
        for (int bb = 0; bb < 4; bb++) {
            const float* hp = hprev + (size_t)(bbase + bb) * HH + k0;
            float4 ha = ldcg4(hp), hb = ldcg4(hp + 4), hc = ldcg4(hp + 8), hd = ldcg4(hp + 12);
            float hk[16] = {ha.x, ha.y, ha.z, ha.w, hb.x, hb.y, hb.z, hb.w,
                            hc.x, hc.y, hc.z, hc.w, hd.x, hd.y, hd.z, hd.w};
#pragma unroll
            for (int k = 0; k < 16; k++) {
                unsigned long long hh = pack2(hk[k], hk[k]);
                fma2(acc2[bb][0], hh, wr2[0][k]);
                fma2(acc2[bb][1], hh, wr2[1][k]);
            }
        }

        // ---- unpack accumulators: v[idx], idx = bb*4 + jj ----
        float v[16];
#pragma unroll
        for (int bb = 0; bb < 4; bb++) {
            float2 lo = unpack2(acc2[bb][0]);
            float2 hi = unpack2(acc2[bb][1]);
            v[bb * 4 + 0] = lo.x; v[bb * 4 + 1] = lo.y;
            v[bb * 4 + 2] = hi.x; v[bb * 4 + 3] = hi.y;
        }

        // ---- log-halving butterfly reduction (16 shfls) ----
#pragma unroll
        for (int i = 0; i < 8; i++) {
            float send = (lane & 1) ? v[i] : v[i + 8];
            float r = __shfl_xor_sync(0xffffffffu, send, 1);
            v[i] = ((lane & 1) ? v[i + 8] : v[i]) + r;
        }
#pragma unroll
        for (int i = 0; i < 4; i++) {
            float send = (lane & 2) ? v[i] : v[i + 4];
            float r = __shfl_xor_sync(0xffffffffu, send, 2);
            v[i] = ((lane & 2) ? v[i + 4] : v[i]) + r;
        }
#pragma unroll
        for (int i = 0; i < 2; i++) {
            float send = (lane & 4) ? v[i] : v[i + 2];
            float r = __shfl_xor_sync(0xffffffffu, send, 4);
            v[i] = ((lane & 4) ? v[i + 2] : v[i]) + r;
        }
        {
            float send = (lane & 8) ? v[0] : v[1];
            float r = __shfl_xor_sync(0xffffffffu, send, 8);
            v[0] = ((lane & 8) ? v[1] : v[0]) + r;
        }
        v[0] += __shfl_xor_sync(0xffffffffu, v[0], 16);

        // ---- epilogue: lanes 0..15 own one (batch, j) pair ----
        if (lane < 16) {
            float pre  = v[0] + bj;
            float hnew = (1.0f - ALPHA) * hold + ALPHA * tanhf(pre);
            __stcg(g_hist + (size_t)t * BB * HH +
                       (size_t)(bbase + bb_e) * HH + j0 + jj_e, hnew);
        }

        __syncthreads();
        if (t < TT - 1) {
            // arrive: one store per CTA (no atomic contention)
            if (tid == 0) {
                __threadfence();  // cumulative: block's h stores visible gpu-wide first
                __stcg(&g_flags[blockIdx.x], (unsigned)(t + 1));
            }

            // overlap: compute x-projection for step t+1 while others arrive
#pragma unroll
            for (int bb = 0; bb < 4; bb++) {
                acc2[bb][0] = 0ULL; acc2[bb][1] = 0ULL;
                float4 xv = __ldg(reinterpret_cast<const float4*>(
                    x + ((size_t)(bbase + bb) * TT + (t + 1)) * II + i0));
                float xs[4] = {xv.x, xv.y, xv.z, xv.w};
#pragma unroll
                for (int i = 0; i < 4; i++) {
                    unsigned long long xx = pack2(xs[i], xs[i]);
                    fma2(acc2[bb][0], xx, wi2[0][i]);
                    fma2(acc2[bb][1], xx, wi2[1][i]);
                }
            }

            // wait: 128 threads poll 128 distinct flags
            if (tid < GRID_R) {
                volatile unsigned* f = (volatile unsigned*)&g_flags[tid];
                while (*f < (unsigned)(t + 1)) {}
            }
            __syncthreads();
        }
    }
}

// ---------------- Output projection: out[b][t][o] = hist[t][b] · W_out[o] + b_out[o] ----------------
#define NTH_O 256
#define KC 64

__global__ void __launch_bounds__(NTH_O) rnn_output(
    const float* __restrict__ Wout,  // [O][H]
    const float* __restrict__ bout,  // [O]
    float* __restrict__ out)         // [B][T][O]
{
    const int t = blockIdx.x;
    __shared__ float sH[BB][KC + 4];
    __shared__ float sW[OO][KC + 4];

    const int tid = threadIdx.x;
    const int og = tid & 15;
    const int bg = tid >> 4;

    float acc[4][4];
#pragma unroll
    for (int i = 0; i < 4; i++)
#pragma unroll
        for (int j = 0; j < 4; j++) acc[i][j] = 0.0f;

    const float* hrow = g_hist + (size_t)t * BB * HH;

    for (int kc = 0; kc < HH; kc += KC) {
        for (int idx = tid; idx < BB * (KC / 4); idx += NTH_O) {
            int row = idx / (KC / 4);
            int c4  = idx % (KC / 4);
            float4 v = *reinterpret_cast<const float4*>(hrow + (size_t)row * HH + kc + c4 * 4);
            sH[row][c4 * 4 + 0] = v.x; sH[row][c4 * 4 + 1] = v.y;
            sH[row][c4 * 4 + 2] = v.z; sH[row][c4 * 4 + 3] = v.w;
        }
        for (int idx = tid; idx < OO * (KC / 4); idx += NTH_O) {
            int row = idx / (KC / 4);
            int c4  = idx % (KC / 4);
            float4 v = *reinterpret_cast<const float4*>(Wout + (size_t)row * HH + kc + c4 * 4);
            sW[row][c4 * 4 + 0] = v.x; sW[row][c4 * 4 + 1] = v.y;
            sW[row][c4 * 4 + 2] = v.z; sW[row][c4 * 4 + 3] = v.w;
        }
        __syncthreads();

#pragma unroll
        for (int k = 0; k < KC; k += 4) {
            float4 hv[4], wv[4];
#pragma unroll
            for (int bb = 0; bb < 4; bb++)
                hv[bb] = *reinterpret_cast<const float4*>(&sH[bg * 4 + bb][k]);
#pragma unroll
            for (int oo = 0; oo < 4; oo++)
                wv[oo] = *reinterpret_cast<const float4*>(&sW[og * 4 + oo][k]);
#pragma unroll
            for (int bb = 0; bb < 4; bb++)
#pragma unroll
                for (int oo = 0; oo < 4; oo++) {
                    acc[bb][oo] = fmaf(hv[bb].x, wv[oo].x, acc[bb][oo]);
                    acc[bb][oo] = fmaf(hv[bb].y, wv[oo].y, acc[bb][oo]);
                    acc[bb][oo] = fmaf(hv[bb].z, wv[oo].z, acc[bb][oo]);
                    acc[bb][oo] = fmaf(hv[bb].w, wv[oo].w, acc[bb][oo]);
                }
        }
        __syncthreads();
    }

#pragma unroll
    for (int oo = 0; oo < 4; oo++) {
        float bo = __ldg(bout + og * 4 + oo);
#pragma unroll
        for (int bb = 0; bb < 4; bb++) {
            int b = bg * 4 + bb;
            int o = og * 4 + oo;
            out[(size_t)b * TT * OO + (size_t)t * OO + o] = acc[bb][oo] + bo;
        }
    }
}

__global__ void copy_hfinal(float* __restrict__ dst) {
    int i = blockIdx.x * blockDim.x + threadIdx.x;
    if (i < BB * HH) dst[i] = g_hist[(size_t)(TT - 1) * BB * HH + i];
}

extern "C" void kernel_launch(void* const* d_in, const int* in_sizes, int n_in,
                              void* d_out, int out_size) {
    const float* x    = (const float*)d_in[0];
    const float* h0   = (const float*)d_in[1];
    const float* Win  = (const float*)d_in[2];
    const float* Wrec = (const float*)d_in[3];
    const float* bias = (const float*)d_in[4];
    const float* Wout = (const float*)d_in[5];
    const float* bout = (const float*)d_in[6];
    float* out = (float*)d_out;

    reset_kernel<<<1, 128>>>();
    rnn_recurrent<<<GRID_R, NTH_R>>>(x, h0, Win, Wrec, bias);
    rnn_output<<<TT, NTH_O>>>(Wout, bout, out);
    if (out_size >= BB * TT * OO + BB * HH) {
        copy_hfinal<<<(BB * HH + 255) / 256, 256>>>(out + (size_t)BB * TT * OO);
    }
}